// round 6
// baseline (speedup 1.0000x reference)
#include <cuda_runtime.h>

// LambdaRankLoss N=8192, 5 integer classes (0..4), SIGMA=1.
//
//   e = exp(p), g = 2^t, rank = stable ascending-by-target order,
//   d_k = 1/log2(k+2) at sorted pos k, G_c = 2^c.
//
//   lambda_i = scale * ( e_i * T1_i - T2_i )
//   T1_i = sum_j (g_j - g_i)(d_i - d_j)/(e_i + e_j)        [pair kernel]
//   T2_i = sum_{c<v_i} (G_c - g_i)(n_c d_i - SD_c)         [O(1), reduce]
//
// Arrays sorted by class; per class segment the (G_c - g_i) factor folds out:
//   inner body per pair: FADD, MUFU.RCP, FADD, FFMA  (MUFU-bound).

#define N        8192
#define K_DCG    512
#define NJS      64
#define JTILE    (N / NJS)       // 128
#define PAIR_T   128
#define ROWS_BLK 256
#define RB       (N / ROWS_BLK)  // 32

__device__ float2 g_sed[N];          // sorted (e, -decay)
__device__ int    g_inv[N];          // sorted pos -> original index
__device__ int    g_seg[8];          // class segment starts, g_seg[5]=N
__device__ float  g_SD[5];           // per-class decay sums
__device__ float  g_scale;           // SIGMA / maxDCG
__device__ float2 g_part[NJS][N / 2];

__device__ __forceinline__ float frcp(float x) {
    float r;
    asm("rcp.approx.f32 %0, %1;" : "=f"(r) : "f"(x));
    return r;
}

// ---------------------------------------------------------------------------
// Fused prep: single block, 1024 threads, 8 elements each.
// ---------------------------------------------------------------------------
__global__ void __launch_bounds__(1024)
prep_fused(const float* __restrict__ pred, const float* __restrict__ tgt) {
    __shared__ int   s_wtot[32][5];
    __shared__ int   s_wpre[32][5];
    __shared__ int   s_tot[5];
    __shared__ int   s_base[6];
    __shared__ float s_red[16];
    __shared__ float s_sdw[32][5];

    const int t    = threadIdx.x;
    const int lane = t & 31;
    const int wid  = t >> 5;
    const int base = t * 8;

    int   v[8];
    int   loc[5] = {0, 0, 0, 0, 0};
    #pragma unroll
    for (int k = 0; k < 8; k++) {
        int c = (int)tgt[base + k];
        c = max(0, min(4, c));
        v[k] = c;
        loc[c]++;
    }

    int inc[5];
    #pragma unroll
    for (int c = 0; c < 5; c++) {
        int x = loc[c];
        #pragma unroll
        for (int o = 1; o < 32; o <<= 1) {
            int y = __shfl_up_sync(0xffffffffu, x, o);
            if (lane >= o) x += y;
        }
        inc[c] = x;
        if (lane == 31) s_wtot[wid][c] = x;
    }
    __syncthreads();

    if (wid == 0) {
        #pragma unroll
        for (int c = 0; c < 5; c++) {
            int own = s_wtot[lane][c];
            int x = own;
            #pragma unroll
            for (int o = 1; o < 32; o <<= 1) {
                int y = __shfl_up_sync(0xffffffffu, x, o);
                if (lane >= o) x += y;
            }
            s_wpre[lane][c] = x - own;
            if (lane == 31) s_tot[c] = x;
        }
        if (lane == 0) {
            int run = 0;
            #pragma unroll
            for (int c = 0; c < 5; c++) { s_base[c] = run; run += s_tot[c]; }
            s_base[5] = N;
            #pragma unroll
            for (int c = 0; c < 6; c++) g_seg[c] = s_base[c];
        }
    }
    __syncthreads();

    int pos[5];
    #pragma unroll
    for (int c = 0; c < 5; c++)
        pos[c] = s_base[c] + s_wpre[wid][c] + (inc[c] - loc[c]);

    float sd[5] = {0.f, 0.f, 0.f, 0.f, 0.f};
    #pragma unroll
    for (int k = 0; k < 8; k++) {
        int c = v[k];
        int kp = pos[c]++;
        float e = __expf(pred[base + k]);
        float d = __fdividef(1.0f, log2f((float)kp + 2.0f));
        g_sed[kp] = make_float2(e, -d);
        g_inv[kp] = base + k;
        sd[c] += d;
    }

    #pragma unroll
    for (int c = 0; c < 5; c++) {
        float x = sd[c];
        #pragma unroll
        for (int o = 16; o > 0; o >>= 1)
            x += __shfl_down_sync(0xffffffffu, x, o);
        if (lane == 0) s_sdw[wid][c] = x;
    }
    __syncthreads();
    if (wid == 0) {
        #pragma unroll
        for (int c = 0; c < 5; c++) {
            float x = s_sdw[lane][c];
            #pragma unroll
            for (int o = 16; o > 0; o >>= 1)
                x += __shfl_down_sync(0xffffffffu, x, o);
            if (lane == 0) g_SD[c] = x;
        }
    }

    // maxDCG over top K_DCG (threads 0..511 => warps 0..15)
    float term = 0.0f;
    if (t < K_DCG) {
        int k  = t + 1;
        int c4 = s_tot[4];
        int c3 = c4 + s_tot[3];
        int c2 = c3 + s_tot[2];
        int c1 = c2 + s_tot[1];
        int c  = (k <= c4) ? 4 : (k <= c3) ? 3 : (k <= c2) ? 2 : (k <= c1) ? 1 : 0;
        term = (exp2f((float)c) - 1.0f) / log2f((float)k + 1.0f);
    }
    {
        float x = term;
        #pragma unroll
        for (int o = 16; o > 0; o >>= 1)
            x += __shfl_down_sync(0xffffffffu, x, o);
        if (wid < 16 && lane == 0) s_red[wid] = x;
        __syncthreads();
        if (t == 0) {
            float s = 0.0f;
            #pragma unroll
            for (int w = 0; w < 16; w++) s += s_red[w];
            g_scale = __fdividef(1.0f, s);                        // SIGMA = 1
        }
    }
}

// ---------------------------------------------------------------------------
// Pairwise: grid (RB, NJS); rows sorted; per-class coefficient folded out.
// ---------------------------------------------------------------------------
__global__ void __launch_bounds__(PAIR_T)
pair_kernel() {
    const int t  = threadIdx.x;
    const int r0 = blockIdx.x * ROWS_BLK + 2 * t;
    const int r1 = r0 + 1;

    const int b1 = g_seg[1], b2 = g_seg[2], b3 = g_seg[3], b4 = g_seg[4];

    const float2 a0 = g_sed[r0];
    const float2 a1 = g_sed[r1];
    const float e0 = a0.x, d0 = -a0.y;
    const float e1 = a1.x, d1 = -a1.y;
    const int v0 = (r0 >= b1) + (r0 >= b2) + (r0 >= b3) + (r0 >= b4);
    const int v1 = (r1 >= b1) + (r1 >= b2) + (r1 >= b3) + (r1 >= b4);
    const float gi0 = (float)(1 << v0);
    const float gi1 = (float)(1 << v1);

    const int s0j = blockIdx.y * JTILE;
    const int s1j = s0j + JTILE;

    float acc0 = 0.0f, acc1 = 0.0f;

    #pragma unroll
    for (int c = 0; c < 5; c++) {
        const int lo = max(g_seg[c], s0j);
        const int hi = min(g_seg[c + 1], s1j);
        if (__all_sync(0xffffffffu, (c == v0) && (c == v1))) continue;

        const float2* __restrict__ p = g_sed + lo;
        int n = hi - lo;                 // may be NEGATIVE if no intersection

        float S0a = 0.f, S0b = 0.f, S1a = 0.f, S1b = 0.f;

        while (n >= 2) {
            const float2 wa = __ldg(p);
            const float2 wb = __ldg(p + 1);
            float sa0 = e0 + wa.x, sb0 = e0 + wb.x;
            float sa1 = e1 + wa.x, sb1 = e1 + wb.x;
            float da0 = d0 + wa.y, db0 = d0 + wb.y;
            float da1 = d1 + wa.y, db1 = d1 + wb.y;
            S0a = fmaf(frcp(sa0), da0, S0a);
            S0b = fmaf(frcp(sb0), db0, S0b);
            S1a = fmaf(frcp(sa1), da1, S1a);
            S1b = fmaf(frcp(sb1), db1, S1b);
            p += 2;
            n -= 2;
        }
        if (n > 0) {                     // FIX: was `if (n)` — negative n truthy
            const float2 wa = __ldg(p);
            S0a = fmaf(frcp(e0 + wa.x), d0 + wa.y, S0a);
            S1a = fmaf(frcp(e1 + wa.x), d1 + wa.y, S1a);
        }

        const float Gc = (float)(1 << c);
        acc0 = fmaf(Gc - gi0, S0a + S0b, acc0);
        acc1 = fmaf(Gc - gi1, S1a + S1b, acc1);
    }

    g_part[blockIdx.y][blockIdx.x * (ROWS_BLK / 2) + t] = make_float2(acc0, acc1);
}

// ---------------------------------------------------------------------------
// Reduce: T1 partials + analytic T2, scatter to original order.
// ---------------------------------------------------------------------------
__global__ void __launch_bounds__(256)
reduce_kernel(float* __restrict__ out) {
    const int k = blockIdx.x * 256 + threadIdx.x;   // sorted position

    float T1 = 0.0f;
    #pragma unroll
    for (int s = 0; s < NJS; s++)
        T1 += ((const float*)g_part[s])[k];

    const int b1 = g_seg[1], b2 = g_seg[2], b3 = g_seg[3], b4 = g_seg[4];
    const int v = (k >= b1) + (k >= b2) + (k >= b3) + (k >= b4);

    const float2 a = g_sed[k];
    const float e = a.x;
    const float d = -a.y;
    const float g = (float)(1 << v);

    float T2 = 0.0f;
    #pragma unroll
    for (int c = 0; c < 4; c++) {
        if (c < v) {
            float nc = (float)(g_seg[c + 1] - g_seg[c]);
            T2 += ((float)(1 << c) - g) * (nc * d - g_SD[c]);
        }
    }

    out[g_inv[k]] = g_scale * (e * T1 - T2);
}

extern "C" void kernel_launch(void* const* d_in, const int* in_sizes, int n_in,
                              void* d_out, int out_size) {
    const float* pred = (const float*)d_in[0];
    const float* tgt  = (const float*)d_in[1];
    float* out        = (float*)d_out;

    prep_fused<<<1, 1024>>>(pred, tgt);
    dim3 grid(RB, NJS);
    pair_kernel<<<grid, PAIR_T>>>();
    reduce_kernel<<<N / 256, 256>>>(out);
}

// round 7
// speedup vs baseline: 1.2195x; 1.2195x over previous
#include <cuda_runtime.h>

// LambdaRankLoss N=8192, 5 integer classes (0..4), SIGMA=1.
//
//   e = exp(p), g = 2^t, rank = stable ascending-by-target order,
//   d_k = 1/log2(k+2) at sorted pos k, G_c = 2^c.
//
//   lambda_i = scale * ( e_i * T1_i - T2_i )
//   T1_i = sum_j (g_j - g_i)(d_i - d_j)/(e_i + e_j)        [pair kernel]
//   T2_i = sum_{c<v_i} (G_c - g_i)(n_c d_i - SD_c)         [O(1), reduce]
//
// Arrays sorted by class; per class segment the (G_c - g_i) factor folds out:
//   inner body per pair: FADD, MUFU.RCP, FADD, FFMA  (MUFU-bound).

#define N        8192
#define NWARPS   (N / 32)        // 256
#define K_DCG    512
#define NJS      64
#define JTILE    (N / NJS)       // 128
#define PAIR_T   128
#define ROWS_BLK 256
#define RB       (N / ROWS_BLK)  // 32
#define PBLK     32              // prep blocks

__device__ float2 g_sed[N];          // sorted (e, -decay)
__device__ int    g_inv[N];          // sorted pos -> original index
__device__ int    g_seg[8];          // class segment starts, g_seg[5]=N
__device__ int    g_wcnt[NWARPS][8]; // per-warp class counts
__device__ int    g_wpre[NWARPS][8]; // classbase + exclusive warp prefix
__device__ float  g_pSD[PBLK][5];    // per-block partial decay sums
__device__ float  g_pDCG[PBLK];      // per-block partial maxDCG
__device__ float2 g_part[NJS][N / 2];

__device__ __forceinline__ float frcp(float x) {
    float r;
    asm("rcp.approx.f32 %0, %1;" : "=f"(r) : "f"(x));
    return r;
}

// ---------------- prep 1: per-warp class counts (no transcendentals) -------
__global__ void __launch_bounds__(256)
prep_count(const float* __restrict__ tgt) {
    const int i    = blockIdx.x * 256 + threadIdx.x;
    const int lane = threadIdx.x & 31;
    const int gw   = i >> 5;
    int v = (int)tgt[i];
    v = max(0, min(4, v));
    #pragma unroll
    for (int c = 0; c < 5; c++) {
        unsigned b = __ballot_sync(0xffffffffu, v == c);
        if (lane == c) g_wcnt[gw][c] = __popc(b);
    }
}

// ---------------- prep 2: scan 256 warp counts -> g_wpre, g_seg ------------
__global__ void __launch_bounds__(256)
prep_scan() {
    __shared__ int s[5][NWARPS];
    __shared__ int s_base[6];

    const int t = threadIdx.x;
    int own[5];
    #pragma unroll
    for (int c = 0; c < 5; c++) { own[c] = g_wcnt[t][c]; s[c][t] = own[c]; }
    __syncthreads();

    for (int ofs = 1; ofs < NWARPS; ofs <<= 1) {
        int a[5] = {0, 0, 0, 0, 0};
        if (t >= ofs) {
            #pragma unroll
            for (int c = 0; c < 5; c++) a[c] = s[c][t - ofs];
        }
        __syncthreads();
        #pragma unroll
        for (int c = 0; c < 5; c++) s[c][t] += a[c];
        __syncthreads();
    }

    if (t == 0) {
        int run = 0;
        #pragma unroll
        for (int c = 0; c < 5; c++) { s_base[c] = run; run += s[c][NWARPS - 1]; }
        s_base[5] = N;
        #pragma unroll
        for (int c = 0; c < 6; c++) g_seg[c] = s_base[c];
    }
    __syncthreads();

    #pragma unroll
    for (int c = 0; c < 5; c++)
        g_wpre[t][c] = s_base[c] + s[c][t] - own[c];       // exclusive
}

// ---------------- prep 3: scatter + per-block SD / maxDCG partials ---------
__global__ void __launch_bounds__(256)
prep_scatter(const float* __restrict__ pred, const float* __restrict__ tgt) {
    __shared__ float s_sd[8][5];
    __shared__ float s_dcg[8];

    const int i    = blockIdx.x * 256 + threadIdx.x;
    const int lane = threadIdx.x & 31;
    const int wid  = threadIdx.x >> 5;
    const int gw   = i >> 5;

    int v = (int)tgt[i];
    v = max(0, min(4, v));

    int intra = 0;
    #pragma unroll
    for (int c = 0; c < 5; c++) {
        unsigned b = __ballot_sync(0xffffffffu, v == c);
        if (v == c) intra = __popc(b & ((1u << lane) - 1u));
    }
    const int k = g_wpre[gw][v] + intra;                   // sorted position

    const float e = __expf(pred[i]);
    const float d = __fdividef(1.0f, log2f((float)k + 2.0f));
    g_sed[k] = make_float2(e, -d);
    g_inv[k] = i;

    // maxDCG term: descending rank r = N - k; included if r <= K_DCG
    float term = 0.0f;
    if (k >= N - K_DCG) {
        int r = N - k;
        term = (exp2f((float)v) - 1.0f) / log2f((float)r + 1.0f);
    }

    // warp reduce per class + dcg
    #pragma unroll
    for (int c = 0; c < 5; c++) {
        float x = (v == c) ? d : 0.0f;
        #pragma unroll
        for (int o = 16; o > 0; o >>= 1)
            x += __shfl_down_sync(0xffffffffu, x, o);
        if (lane == 0) s_sd[wid][c] = x;
    }
    {
        float x = term;
        #pragma unroll
        for (int o = 16; o > 0; o >>= 1)
            x += __shfl_down_sync(0xffffffffu, x, o);
        if (lane == 0) s_dcg[wid] = x;
    }
    __syncthreads();

    if (threadIdx.x < 5) {
        float s = 0.0f;
        #pragma unroll
        for (int w = 0; w < 8; w++) s += s_sd[w][threadIdx.x];
        g_pSD[blockIdx.x][threadIdx.x] = s;
    } else if (threadIdx.x == 5) {
        float s = 0.0f;
        #pragma unroll
        for (int w = 0; w < 8; w++) s += s_dcg[w];
        g_pDCG[blockIdx.x] = s;
    }
}

// ---------------- pairwise: grid (RB, NJS) --------------------------------
__global__ void __launch_bounds__(PAIR_T)
pair_kernel() {
    const int t  = threadIdx.x;
    const int r0 = blockIdx.x * ROWS_BLK + 2 * t;
    const int r1 = r0 + 1;

    const int b1 = g_seg[1], b2 = g_seg[2], b3 = g_seg[3], b4 = g_seg[4];

    const float2 a0 = g_sed[r0];
    const float2 a1 = g_sed[r1];
    const float e0 = a0.x, d0 = -a0.y;
    const float e1 = a1.x, d1 = -a1.y;
    const int v0 = (r0 >= b1) + (r0 >= b2) + (r0 >= b3) + (r0 >= b4);
    const int v1 = (r1 >= b1) + (r1 >= b2) + (r1 >= b3) + (r1 >= b4);
    const float gi0 = (float)(1 << v0);
    const float gi1 = (float)(1 << v1);

    const int s0j = blockIdx.y * JTILE;
    const int s1j = s0j + JTILE;

    float acc0 = 0.0f, acc1 = 0.0f;

    #pragma unroll
    for (int c = 0; c < 5; c++) {
        const int lo = max(g_seg[c], s0j);
        const int hi = min(g_seg[c + 1], s1j);
        if (__all_sync(0xffffffffu, (c == v0) && (c == v1))) continue;

        const float2* __restrict__ p = g_sed + lo;
        int n = hi - lo;                 // negative if no intersection

        float S0a = 0.f, S0b = 0.f, S1a = 0.f, S1b = 0.f;

        while (n >= 2) {
            const float2 wa = __ldg(p);
            const float2 wb = __ldg(p + 1);
            float sa0 = e0 + wa.x, sb0 = e0 + wb.x;
            float sa1 = e1 + wa.x, sb1 = e1 + wb.x;
            float da0 = d0 + wa.y, db0 = d0 + wb.y;
            float da1 = d1 + wa.y, db1 = d1 + wb.y;
            S0a = fmaf(frcp(sa0), da0, S0a);
            S0b = fmaf(frcp(sb0), db0, S0b);
            S1a = fmaf(frcp(sa1), da1, S1a);
            S1b = fmaf(frcp(sb1), db1, S1b);
            p += 2;
            n -= 2;
        }
        if (n > 0) {
            const float2 wa = __ldg(p);
            S0a = fmaf(frcp(e0 + wa.x), d0 + wa.y, S0a);
            S1a = fmaf(frcp(e1 + wa.x), d1 + wa.y, S1a);
        }

        const float Gc = (float)(1 << c);
        acc0 = fmaf(Gc - gi0, S0a + S0b, acc0);
        acc1 = fmaf(Gc - gi1, S1a + S1b, acc1);
    }

    g_part[blockIdx.y][blockIdx.x * (ROWS_BLK / 2) + t] = make_float2(acc0, acc1);
}

// ---------------- reduce: finish SD/DCG partials, T1 + T2, scatter out -----
__global__ void __launch_bounds__(256)
reduce_kernel(float* __restrict__ out) {
    __shared__ float s_scale;
    __shared__ float s_SD[5];

    const int t    = threadIdx.x;
    const int lane = t & 31;
    const int wid  = t >> 5;

    // warp 0: maxDCG partials -> scale; warps 1..5: SD class partials
    if (wid == 0) {
        float x = g_pDCG[lane];                     // PBLK == 32
        #pragma unroll
        for (int o = 16; o > 0; o >>= 1)
            x += __shfl_down_sync(0xffffffffu, x, o);
        if (lane == 0) s_scale = __fdividef(1.0f, x);       // SIGMA = 1
    } else if (wid <= 5) {
        float x = g_pSD[lane][wid - 1];
        #pragma unroll
        for (int o = 16; o > 0; o >>= 1)
            x += __shfl_down_sync(0xffffffffu, x, o);
        if (lane == 0) s_SD[wid - 1] = x;
    }
    __syncthreads();

    const int k = blockIdx.x * 256 + t;             // sorted position

    float T1 = 0.0f;
    #pragma unroll
    for (int s = 0; s < NJS; s++)
        T1 += ((const float*)g_part[s])[k];

    const int b1 = g_seg[1], b2 = g_seg[2], b3 = g_seg[3], b4 = g_seg[4];
    const int v = (k >= b1) + (k >= b2) + (k >= b3) + (k >= b4);

    const float2 a = g_sed[k];
    const float e = a.x;
    const float d = -a.y;
    const float g = (float)(1 << v);

    float T2 = 0.0f;
    #pragma unroll
    for (int c = 0; c < 4; c++) {
        if (c < v) {
            float nc = (float)(g_seg[c + 1] - g_seg[c]);
            T2 += ((float)(1 << c) - g) * (nc * d - s_SD[c]);
        }
    }

    out[g_inv[k]] = s_scale * (e * T1 - T2);
}

extern "C" void kernel_launch(void* const* d_in, const int* in_sizes, int n_in,
                              void* d_out, int out_size) {
    const float* pred = (const float*)d_in[0];
    const float* tgt  = (const float*)d_in[1];
    float* out        = (float*)d_out;

    prep_count<<<PBLK, 256>>>(tgt);
    prep_scan<<<1, 256>>>();
    prep_scatter<<<PBLK, 256>>>(pred, tgt);
    dim3 grid(RB, NJS);
    pair_kernel<<<grid, PAIR_T>>>();
    reduce_kernel<<<N / 256, 256>>>(out);
}

// round 8
// speedup vs baseline: 1.2794x; 1.0491x over previous
#include <cuda_runtime.h>

// LambdaRankLoss N=8192, 5 integer classes (0..4), SIGMA=1.
//
//   e = exp(p), g = 2^t, d = 1/log2(rank+1), rank = stable ascending-by-target.
//   w_ij = (g_j - g_i)(d_i - d_j) >= 0
//   lam_ij = e_i * w_ij / (e_i + e_j)  -  [t_j < t_i] * w_ij
//   lambda_i = scale * ( e_i * T1_i - T2_i ),  scale = 1/maxDCG
//   T1_i = sum_j w_ij / (e_i + e_j)                      [branchless pair kernel]
//   T2_i = sum_{c < v_i} (G_c - g_i)(n_c d_i - SD_c)     [O(1) in reduce]

#define N        8192
#define NWARPS   (N / 32)        // 256
#define K_DCG    512
#define NJS      64
#define JTILE    (N / NJS)       // 128
#define PAIR_T   128
#define ROWS_BLK 256
#define RB       (N / ROWS_BLK)  // 32
#define PBLK     32

typedef unsigned long long ull;

__device__ float  g_e[N];            // exp(pred), original order
__device__ float  g_nd[N];           // -decay, original order
__device__ float  g_g[N];            // 2^class, original order
__device__ int    g_seg[8];          // class segment bounds (counts for T2)
__device__ int    g_wcnt[NWARPS][8];
__device__ int    g_wpre[NWARPS][8];
__device__ float  g_pSD[PBLK][5];
__device__ float  g_pDCG[PBLK];
__device__ float2 g_part[NJS][N / 2];

// ---------------- packed f32x2 helpers ----------------
__device__ __forceinline__ ull pk2(float x, float y) {
    ull r;
    asm("mov.b64 %0, {%1, %2};" : "=l"(r) : "f"(x), "f"(y));
    return r;
}
__device__ __forceinline__ float2 unpk2(ull p) {
    float2 r;
    asm("mov.b64 {%0, %1}, %2;" : "=f"(r.x), "=f"(r.y) : "l"(p));
    return r;
}
__device__ __forceinline__ ull f2add(ull a, ull b) {
    ull c;
    asm("add.rn.f32x2 %0, %1, %2;" : "=l"(c) : "l"(a), "l"(b));
    return c;
}
__device__ __forceinline__ ull f2mul(ull a, ull b) {
    ull c;
    asm("mul.rn.f32x2 %0, %1, %2;" : "=l"(c) : "l"(a), "l"(b));
    return c;
}
__device__ __forceinline__ ull f2fma(ull a, ull b, ull c) {
    ull d;
    asm("fma.rn.f32x2 %0, %1, %2, %3;" : "=l"(d) : "l"(a), "l"(b), "l"(c));
    return d;
}
__device__ __forceinline__ ull f2rcp(ull a) {
    ull c;
    asm("{\n\t.reg .f32 lo, hi;\n\t"
        "mov.b64 {lo, hi}, %1;\n\t"
        "rcp.approx.f32 lo, lo;\n\t"
        "rcp.approx.f32 hi, hi;\n\t"
        "mov.b64 %0, {lo, hi};\n\t}"
        : "=l"(c) : "l"(a));
    return c;
}

// ---------------- prep 1: per-warp class counts ----------------
__global__ void __launch_bounds__(256)
prep_count(const float* __restrict__ tgt) {
    const int i    = blockIdx.x * 256 + threadIdx.x;
    const int lane = threadIdx.x & 31;
    const int gw   = i >> 5;
    int v = (int)tgt[i];
    v = max(0, min(4, v));
    #pragma unroll
    for (int c = 0; c < 5; c++) {
        unsigned b = __ballot_sync(0xffffffffu, v == c);
        if (lane == c) g_wcnt[gw][c] = __popc(b);
    }
}

// ---------------- prep 2: scan warp counts -> g_wpre, g_seg ----------------
__global__ void __launch_bounds__(256)
prep_scan() {
    __shared__ int s[5][NWARPS];
    __shared__ int s_base[6];

    const int t = threadIdx.x;
    int own[5];
    #pragma unroll
    for (int c = 0; c < 5; c++) { own[c] = g_wcnt[t][c]; s[c][t] = own[c]; }
    __syncthreads();

    for (int ofs = 1; ofs < NWARPS; ofs <<= 1) {
        int a[5] = {0, 0, 0, 0, 0};
        if (t >= ofs) {
            #pragma unroll
            for (int c = 0; c < 5; c++) a[c] = s[c][t - ofs];
        }
        __syncthreads();
        #pragma unroll
        for (int c = 0; c < 5; c++) s[c][t] += a[c];
        __syncthreads();
    }

    if (t == 0) {
        int run = 0;
        #pragma unroll
        for (int c = 0; c < 5; c++) { s_base[c] = run; run += s[c][NWARPS - 1]; }
        s_base[5] = N;
        #pragma unroll
        for (int c = 0; c < 6; c++) g_seg[c] = s_base[c];
    }
    __syncthreads();

    #pragma unroll
    for (int c = 0; c < 5; c++)
        g_wpre[t][c] = s_base[c] + s[c][t] - own[c];       // exclusive
}

// ---------------- prep 3: e, -d, g in ORIGINAL order + SD/DCG partials -----
__global__ void __launch_bounds__(256)
prep_vals(const float* __restrict__ pred, const float* __restrict__ tgt) {
    __shared__ float s_sd[8][5];
    __shared__ float s_dcg[8];

    const int i    = blockIdx.x * 256 + threadIdx.x;
    const int lane = threadIdx.x & 31;
    const int wid  = threadIdx.x >> 5;
    const int gw   = i >> 5;

    int v = (int)tgt[i];
    v = max(0, min(4, v));

    int intra = 0;
    #pragma unroll
    for (int c = 0; c < 5; c++) {
        unsigned b = __ballot_sync(0xffffffffu, v == c);
        if (v == c) intra = __popc(b & ((1u << lane) - 1u));
    }
    const int k = g_wpre[gw][v] + intra;       // sorted position (rank-1)

    const float e = __expf(pred[i]);
    const float d = __fdividef(1.0f, log2f((float)k + 2.0f));
    g_e[i]  = e;
    g_nd[i] = -d;
    g_g[i]  = (float)(1 << v);

    float term = 0.0f;
    if (k >= N - K_DCG) {
        int r = N - k;                          // descending rank
        term = (exp2f((float)v) - 1.0f) / log2f((float)r + 1.0f);
    }

    #pragma unroll
    for (int c = 0; c < 5; c++) {
        float x = (v == c) ? d : 0.0f;
        #pragma unroll
        for (int o = 16; o > 0; o >>= 1)
            x += __shfl_down_sync(0xffffffffu, x, o);
        if (lane == 0) s_sd[wid][c] = x;
    }
    {
        float x = term;
        #pragma unroll
        for (int o = 16; o > 0; o >>= 1)
            x += __shfl_down_sync(0xffffffffu, x, o);
        if (lane == 0) s_dcg[wid] = x;
    }
    __syncthreads();

    if (threadIdx.x < 5) {
        float s = 0.0f;
        #pragma unroll
        for (int w = 0; w < 8; w++) s += s_sd[w][threadIdx.x];
        g_pSD[blockIdx.x][threadIdx.x] = s;
    } else if (threadIdx.x == 5) {
        float s = 0.0f;
        #pragma unroll
        for (int w = 0; w < 8; w++) s += s_dcg[w];
        g_pDCG[blockIdx.x] = s;
    }
}

// ---------------- pairwise: branchless, packed f32x2, static trip count ----
__global__ void __launch_bounds__(PAIR_T)
pair_kernel() {
    const int t  = threadIdx.x;
    const int r0 = blockIdx.x * ROWS_BLK + 2 * t;
    const int r1 = r0 + 1;

    const float e0 = g_e[r0],  e1 = g_e[r1];
    const float d0 = -g_nd[r0], d1 = -g_nd[r1];
    const float gg0 = g_g[r0], gg1 = g_g[r1];

    const ull E0  = pk2(e0, e0),    E1  = pk2(e1, e1);
    const ull D0  = pk2(d0, d0),    D1  = pk2(d1, d1);
    const ull NG0 = pk2(-gg0, -gg0), NG1 = pk2(-gg1, -gg1);

    const int jbase = blockIdx.y * JTILE;
    const ull* __restrict__ pe  = (const ull*)(g_e  + jbase);
    const ull* __restrict__ pnd = (const ull*)(g_nd + jbase);
    const ull* __restrict__ pg  = (const ull*)(g_g  + jbase);

    ull acc0 = 0ull, acc1 = 0ull;   // (0.0f, 0.0f)

    #pragma unroll 8
    for (int j = 0; j < JTILE / 2; j++) {
        const ull ej  = __ldg(pe + j);      // warp-uniform -> broadcast
        const ull ndj = __ldg(pnd + j);
        const ull gj  = __ldg(pg + j);

        // row 0: acc += (g_j - g0)(d0 - d_j) * rcp(e0 + e_j)
        {
            ull s  = f2add(E0, ej);
            ull r  = f2rcp(s);
            ull gd = f2add(gj, NG0);
            ull dd = f2add(D0, ndj);
            acc0 = f2fma(f2mul(gd, dd), r, acc0);
        }
        // row 1
        {
            ull s  = f2add(E1, ej);
            ull r  = f2rcp(s);
            ull gd = f2add(gj, NG1);
            ull dd = f2add(D1, ndj);
            acc1 = f2fma(f2mul(gd, dd), r, acc1);
        }
    }

    float2 a0 = unpk2(acc0);
    float2 a1 = unpk2(acc1);
    g_part[blockIdx.y][blockIdx.x * (ROWS_BLK / 2) + t] =
        make_float2(a0.x + a0.y, a1.x + a1.y);
}

// ---------------- reduce: finish SD/DCG, T1 + analytic T2 ----------------
__global__ void __launch_bounds__(256)
reduce_kernel(const float* __restrict__ tgt, float* __restrict__ out) {
    __shared__ float s_scale;
    __shared__ float s_SD[5];

    const int t    = threadIdx.x;
    const int lane = t & 31;
    const int wid  = t >> 5;

    if (wid == 0) {
        float x = g_pDCG[lane];                    // PBLK == 32
        #pragma unroll
        for (int o = 16; o > 0; o >>= 1)
            x += __shfl_down_sync(0xffffffffu, x, o);
        if (lane == 0) s_scale = __fdividef(1.0f, x);
    } else if (wid <= 5) {
        float x = g_pSD[lane][wid - 1];
        #pragma unroll
        for (int o = 16; o > 0; o >>= 1)
            x += __shfl_down_sync(0xffffffffu, x, o);
        if (lane == 0) s_SD[wid - 1] = x;
    }
    __syncthreads();

    const int i = blockIdx.x * 256 + t;            // original index

    float T1 = 0.0f;
    #pragma unroll
    for (int s = 0; s < NJS; s++)
        T1 += ((const float*)g_part[s])[i];

    int v = (int)tgt[i];
    v = max(0, min(4, v));

    const float e = g_e[i];
    const float d = -g_nd[i];
    const float g = (float)(1 << v);

    float T2 = 0.0f;
    #pragma unroll
    for (int c = 0; c < 4; c++) {
        if (c < v) {
            float nc = (float)(g_seg[c + 1] - g_seg[c]);
            T2 += ((float)(1 << c) - g) * (nc * d - s_SD[c]);
        }
    }

    out[i] = s_scale * (e * T1 - T2);
}

extern "C" void kernel_launch(void* const* d_in, const int* in_sizes, int n_in,
                              void* d_out, int out_size) {
    const float* pred = (const float*)d_in[0];
    const float* tgt  = (const float*)d_in[1];
    float* out        = (float*)d_out;

    prep_count<<<PBLK, 256>>>(tgt);
    prep_scan<<<1, 256>>>();
    prep_vals<<<PBLK, 256>>>(pred, tgt);
    dim3 grid(RB, NJS);
    pair_kernel<<<grid, PAIR_T>>>();
    reduce_kernel<<<N / 256, 256>>>(tgt, out);
}

// round 9
// speedup vs baseline: 1.2873x; 1.0062x over previous
#include <cuda_runtime.h>

// LambdaRankLoss N=8192, 5 integer classes (0..4), SIGMA=1.
//
//   e = exp(p), g = 2^t, d = 1/log2(rank+1), rank = stable ascending-by-target.
//   lambda_i = scale * ( e_i * T1_i - T2_i ),  scale = 1/maxDCG
//   T1_i = sum_j (g_j - g_i)(d_i - d_j)/(e_i + e_j)
//        = sum_c (G_c - g_i) * ( d_i * Q_c + S_c ),
//          Q_c = sum_{j in c} r_ij,  S_c = sum_{j in c} (-d_j) r_ij
//   T2_i = sum_{c < v_i} (G_c - g_i)(n_c d_i - SD_c)     [O(1), reduce]
//
// Both rows and j sorted by class: 4-op inner body (3 fma-pipe + 1 MUFU),
// chunk-of-4 unrolled dynamic loop; most j-tiles are single-class.

#define N        8192
#define NWARPS   (N / 32)        // 256
#define K_DCG    512
#define NJS      64
#define JTILE    (N / NJS)       // 128
#define PAIR_T   128
#define ROWS_BLK 256
#define RB       (N / ROWS_BLK)  // 32
#define PBLK     32

__device__ float2 g_sed[N];          // sorted (e, -decay)
__device__ int    g_inv[N];          // sorted pos -> original index
__device__ int    g_seg[8];          // class segment bounds
__device__ int    g_wcnt[NWARPS][8];
__device__ int    g_wpre[NWARPS][8];
__device__ float  g_pSD[PBLK][5];
__device__ float  g_pDCG[PBLK];
__device__ float2 g_part[NJS][N / 2];

__device__ __forceinline__ float frcp(float x) {
    float r;
    asm("rcp.approx.f32 %0, %1;" : "=f"(r) : "f"(x));
    return r;
}

// ---------------- prep 1: per-warp class counts ----------------
__global__ void __launch_bounds__(256)
prep_count(const float* __restrict__ tgt) {
    const int i    = blockIdx.x * 256 + threadIdx.x;
    const int lane = threadIdx.x & 31;
    const int gw   = i >> 5;
    int v = (int)tgt[i];
    v = max(0, min(4, v));
    #pragma unroll
    for (int c = 0; c < 5; c++) {
        unsigned b = __ballot_sync(0xffffffffu, v == c);
        if (lane == c) g_wcnt[gw][c] = __popc(b);
    }
}

// ---------------- prep 2: scan warp counts -> g_wpre, g_seg ----------------
__global__ void __launch_bounds__(256)
prep_scan() {
    __shared__ int s[5][NWARPS];
    __shared__ int s_base[6];

    const int t = threadIdx.x;
    int own[5];
    #pragma unroll
    for (int c = 0; c < 5; c++) { own[c] = g_wcnt[t][c]; s[c][t] = own[c]; }
    __syncthreads();

    for (int ofs = 1; ofs < NWARPS; ofs <<= 1) {
        int a[5] = {0, 0, 0, 0, 0};
        if (t >= ofs) {
            #pragma unroll
            for (int c = 0; c < 5; c++) a[c] = s[c][t - ofs];
        }
        __syncthreads();
        #pragma unroll
        for (int c = 0; c < 5; c++) s[c][t] += a[c];
        __syncthreads();
    }

    if (t == 0) {
        int run = 0;
        #pragma unroll
        for (int c = 0; c < 5; c++) { s_base[c] = run; run += s[c][NWARPS - 1]; }
        s_base[5] = N;
        #pragma unroll
        for (int c = 0; c < 6; c++) g_seg[c] = s_base[c];
    }
    __syncthreads();

    #pragma unroll
    for (int c = 0; c < 5; c++)
        g_wpre[t][c] = s_base[c] + s[c][t] - own[c];       // exclusive
}

// ---------------- prep 3: sorted scatter + SD / maxDCG partials ------------
__global__ void __launch_bounds__(256)
prep_scatter(const float* __restrict__ pred, const float* __restrict__ tgt) {
    __shared__ float s_sd[8][5];
    __shared__ float s_dcg[8];

    const int i    = blockIdx.x * 256 + threadIdx.x;
    const int lane = threadIdx.x & 31;
    const int wid  = threadIdx.x >> 5;
    const int gw   = i >> 5;

    int v = (int)tgt[i];
    v = max(0, min(4, v));

    int intra = 0;
    #pragma unroll
    for (int c = 0; c < 5; c++) {
        unsigned b = __ballot_sync(0xffffffffu, v == c);
        if (v == c) intra = __popc(b & ((1u << lane) - 1u));
    }
    const int k = g_wpre[gw][v] + intra;       // sorted position (rank-1)

    const float e = __expf(pred[i]);
    const float d = __fdividef(1.0f, log2f((float)k + 2.0f));
    g_sed[k] = make_float2(e, -d);
    g_inv[k] = i;

    float term = 0.0f;
    if (k >= N - K_DCG) {
        int r = N - k;                          // descending rank
        term = (exp2f((float)v) - 1.0f) / log2f((float)r + 1.0f);
    }

    #pragma unroll
    for (int c = 0; c < 5; c++) {
        float x = (v == c) ? d : 0.0f;
        #pragma unroll
        for (int o = 16; o > 0; o >>= 1)
            x += __shfl_down_sync(0xffffffffu, x, o);
        if (lane == 0) s_sd[wid][c] = x;
    }
    {
        float x = term;
        #pragma unroll
        for (int o = 16; o > 0; o >>= 1)
            x += __shfl_down_sync(0xffffffffu, x, o);
        if (lane == 0) s_dcg[wid] = x;
    }
    __syncthreads();

    if (threadIdx.x < 5) {
        float s = 0.0f;
        #pragma unroll
        for (int w = 0; w < 8; w++) s += s_sd[w][threadIdx.x];
        g_pSD[blockIdx.x][threadIdx.x] = s;
    } else if (threadIdx.x == 5) {
        float s = 0.0f;
        #pragma unroll
        for (int w = 0; w < 8; w++) s += s_dcg[w];
        g_pDCG[blockIdx.x] = s;
    }
}

// ---------------- pairwise: 4-op body, chunk-unrolled segments -------------
__global__ void __launch_bounds__(PAIR_T)
pair_kernel() {
    const int t  = threadIdx.x;
    const int r0 = blockIdx.x * ROWS_BLK + 2 * t;
    const int r1 = r0 + 1;

    const int b1 = g_seg[1], b2 = g_seg[2], b3 = g_seg[3], b4 = g_seg[4];

    const float2 a0 = g_sed[r0];
    const float2 a1 = g_sed[r1];
    const float e0 = a0.x, d0 = -a0.y;
    const float e1 = a1.x, d1 = -a1.y;
    const int v0 = (r0 >= b1) + (r0 >= b2) + (r0 >= b3) + (r0 >= b4);
    const int v1 = (r1 >= b1) + (r1 >= b2) + (r1 >= b3) + (r1 >= b4);
    const float gi0 = (float)(1 << v0);
    const float gi1 = (float)(1 << v1);

    const int s0j = blockIdx.y * JTILE;
    const int s1j = s0j + JTILE;

    float acc0 = 0.0f, acc1 = 0.0f;

    #pragma unroll
    for (int c = 0; c < 5; c++) {
        const int lo = max(g_seg[c], s0j);
        const int hi = min(g_seg[c + 1], s1j);
        int n = hi - lo;                         // block-uniform
        if (n <= 0) continue;                    // uniform branch, cheap
        if (__all_sync(0xffffffffu, (c == v0) && (c == v1))) continue;

        const float2* __restrict__ p = g_sed + lo;

        float Q0 = 0.f, S0 = 0.f, Q1 = 0.f, S1 = 0.f;

        while (n >= 4) {
            #pragma unroll
            for (int u = 0; u < 4; u++) {
                const float2 w = __ldg(p + u);   // warp-uniform -> broadcast
                float ra = frcp(e0 + w.x);
                float rb = frcp(e1 + w.x);
                Q0 += ra;
                S0 = fmaf(w.y, ra, S0);
                Q1 += rb;
                S1 = fmaf(w.y, rb, S1);
            }
            p += 4;
            n -= 4;
        }
        while (n > 0) {
            const float2 w = __ldg(p);
            float ra = frcp(e0 + w.x);
            float rb = frcp(e1 + w.x);
            Q0 += ra;
            S0 = fmaf(w.y, ra, S0);
            Q1 += rb;
            S1 = fmaf(w.y, rb, S1);
            p++;
            n--;
        }

        const float Gc = (float)(1 << c);
        acc0 = fmaf(Gc - gi0, fmaf(d0, Q0, S0), acc0);
        acc1 = fmaf(Gc - gi1, fmaf(d1, Q1, S1), acc1);
    }

    g_part[blockIdx.y][blockIdx.x * (ROWS_BLK / 2) + t] = make_float2(acc0, acc1);
}

// ---------------- reduce: finish SD/DCG, T1 + analytic T2, scatter ---------
__global__ void __launch_bounds__(256)
reduce_kernel(float* __restrict__ out) {
    __shared__ float s_scale;
    __shared__ float s_SD[5];

    const int t    = threadIdx.x;
    const int lane = t & 31;
    const int wid  = t >> 5;

    if (wid == 0) {
        float x = g_pDCG[lane];                    // PBLK == 32
        #pragma unroll
        for (int o = 16; o > 0; o >>= 1)
            x += __shfl_down_sync(0xffffffffu, x, o);
        if (lane == 0) s_scale = __fdividef(1.0f, x);
    } else if (wid <= 5) {
        float x = g_pSD[lane][wid - 1];
        #pragma unroll
        for (int o = 16; o > 0; o >>= 1)
            x += __shfl_down_sync(0xffffffffu, x, o);
        if (lane == 0) s_SD[wid - 1] = x;
    }
    __syncthreads();

    const int k = blockIdx.x * 256 + t;            // sorted position

    float T1 = 0.0f;
    #pragma unroll
    for (int s = 0; s < NJS; s++)
        T1 += ((const float*)g_part[s])[k];

    const int b1 = g_seg[1], b2 = g_seg[2], b3 = g_seg[3], b4 = g_seg[4];
    const int v = (k >= b1) + (k >= b2) + (k >= b3) + (k >= b4);

    const float2 a = g_sed[k];
    const float e = a.x;
    const float d = -a.y;
    const float g = (float)(1 << v);

    float T2 = 0.0f;
    #pragma unroll
    for (int c = 0; c < 4; c++) {
        if (c < v) {
            float nc = (float)(g_seg[c + 1] - g_seg[c]);
            T2 += ((float)(1 << c) - g) * (nc * d - s_SD[c]);
        }
    }

    out[g_inv[k]] = s_scale * (e * T1 - T2);
}

extern "C" void kernel_launch(void* const* d_in, const int* in_sizes, int n_in,
                              void* d_out, int out_size) {
    const float* pred = (const float*)d_in[0];
    const float* tgt  = (const float*)d_in[1];
    float* out        = (float*)d_out;

    prep_count<<<PBLK, 256>>>(tgt);
    prep_scan<<<1, 256>>>();
    prep_scatter<<<PBLK, 256>>>(pred, tgt);
    dim3 grid(RB, NJS);
    pair_kernel<<<grid, PAIR_T>>>();
    reduce_kernel<<<N / 256, 256>>>(out);
}